// round 14
// baseline (speedup 1.0000x reference)
#include <cuda_runtime.h>

// DigitCaps dynamic routing, GB300 sm_103a — R14.
// B=64, I=4096, Din=8, N=10, D=16, 3 routing iterations.
//
// R14 = R13 (104.96, 16-replica atomics WIN) + specialized k_pass0:
//  - pass0 = bare einsum + uniform sum: quad-buffered W via cp.async,
//    ONE barrier per 2 il (14 vs 28), no softmax/logit/agreement code at all
//  - pass1/2 + replica reduction path unchanged (protect the win)

#define B_ 64
#define I_ 4096
#define P_ 8
#define N_ 10
#define D_ 16
#define ND_ 160
#define THREADS 320              // 32 b x 10 n, lane = 16bb x 2dh, BTILE=2
#define OUT_ (B_ * ND_)          // 10240
#define NREP 16
#define L2E 1.4426950408889634f

#define SX_STRIDE 236
#define SX_SZ (32 * SX_STRIDE)   // 7552 floats
#define SW_SZ (2 * 1280)
#define SE_SZ (2 * 352)
#define SMEM_BYTES ((SX_SZ + SW_SZ + SE_SZ) * 4)     // 43,264 B (pass1/2)
#define SMEM0_BYTES ((SX_SZ + 4 * 1280) * 4)          // 50,688 B (pass0, quad W)

__device__ float g_srep[3][NREP][OUT_];         // replicated atomic accumulators, 2MB
__device__ float g_blog[(size_t)I_ * 640];      // log2-domain logits [i][n*64+bh*32+l]
__device__ float g_v[OUT_];                     // squashed v

typedef unsigned long long ull;

static __device__ __forceinline__ ull pack2(float a, float b) {
    ull r; asm("mov.b64 %0, {%1,%2};" : "=l"(r) : "f"(a), "f"(b)); return r;
}
static __device__ __forceinline__ float2 unpack2(ull v) {
    float2 r; asm("mov.b64 {%0,%1}, %2;" : "=f"(r.x), "=f"(r.y) : "l"(v)); return r;
}
static __device__ __forceinline__ ull ffma2(ull a, ull b, ull c) {
    ull d; asm("fma.rn.f32x2 %0, %1, %2, %3;" : "=l"(d) : "l"(a), "l"(b), "l"(c)); return d;
}
static __device__ __forceinline__ ull fadd2(ull a, ull b) {
    ull d; asm("add.rn.f32x2 %0, %1, %2;" : "=l"(d) : "l"(a), "l"(b)); return d;
}
static __device__ __forceinline__ float fast_ex2(float x) {
    float r; asm("ex2.approx.f32 %0, %1;" : "=f"(r) : "f"(x)); return r;
}
static __device__ __forceinline__ void cp16(unsigned dst, const void* src) {
    asm volatile("cp.async.cg.shared.global [%0], [%1], 16;" :: "r"(dst), "l"(src));
}
static __device__ __forceinline__ void cp_commit() {
    asm volatile("cp.async.commit_group;");
}
static __device__ __forceinline__ void cp_wait0() {
    asm volatile("cp.async.wait_group 0;" ::: "memory");
}

// launch #0: zero all replica sets
__global__ __launch_bounds__(256) void k_pad() {
    int idx = blockIdx.x * 256 + threadIdx.x;
    if (idx < 3 * NREP * OUT_) ((float*)g_srep)[idx] = 0.0f;
}

// ============================================================================
// pass0: bare einsum + uniform-c sum. Quad-buffered W, barrier per 2 il.
// ============================================================================
__global__ __launch_bounds__(THREADS, 2) void k_pass0(const float* __restrict__ X,
                                                      const float* __restrict__ W) {
    extern __shared__ float smem[];
    float* s_x = smem;                 // [lb][r] stride SX_STRIDE
    float* s_w = smem + SX_SZ;         // 4 x 1280

    const int tid = threadIdx.x;
    const int n   = tid >> 5;
    const int l   = tid & 31;
    const int bb  = l & 15;
    const int dh  = l >> 4;
    const int cb  = blockIdx.x;
    const int bh  = blockIdx.y;
    int i0, ni;
    if (cb < 100) { i0 = cb * 28; ni = 28; }
    else          { i0 = 2800 + (cb - 100) * 27; ni = 27; }
    const int b1 = bh * 32 + bb;
    const int b2 = b1 + 16;

    // stage x
    {
        int nr = ni * 8;
        for (int idx = tid; idx < 32 * nr; idx += THREADS) {
            int lb = idx / nr;
            int r  = idx - lb * nr;
            s_x[lb * SX_STRIDE + r] = X[(size_t)(bh * 32 + lb) * (I_ * P_) + i0 * P_ + r];
        }
    }
    // stage W(0), W(1)
    unsigned swb = (unsigned)__cvta_generic_to_shared(s_w);
    cp16(swb + tid * 16, W + (size_t)i0 * 1280 + tid * 4);
    if (ni > 1) cp16(swb + 5120 + tid * 16, W + (size_t)(i0 + 1) * 1280 + tid * 4);
    cp_commit();
    cp_wait0();
    __syncthreads();

    ull sa[4], sb[4];
#pragma unroll
    for (int j = 0; j < 4; j++) { sa[j] = 0ULL; sb[j] = 0ULL; }

    const float4* sxa = (const float4*)(s_x + bb * SX_STRIDE);
    const float4* sxb = (const float4*)(s_x + (bb + 16) * SX_STRIDE);

    int ip = 0;
    for (; ip + 1 < ni; ip += 2) {
        // stage W(ip+2), W(ip+3): their slots were consumed before the LAST barrier
        if (ip + 2 < ni) {
            cp16(swb + ((ip + 2) & 3) * 5120 + tid * 16,
                 W + (size_t)(i0 + ip + 2) * 1280 + tid * 4);
            if (ip + 3 < ni)
                cp16(swb + ((ip + 3) & 3) * 5120 + tid * 16,
                     W + (size_t)(i0 + ip + 3) * 1280 + tid * 4);
            cp_commit();
        }
#pragma unroll
        for (int j2 = 0; j2 < 2; j2++) {
            const int il = ip + j2;
            const float4* xra = sxa + il * 2;
            const float4* xrb = sxb + il * 2;
            float4 a0 = xra[0], a1 = xra[1], c0 = xrb[0], c1 = xrb[1];
            float xa[8] = {a0.x, a0.y, a0.z, a0.w, a1.x, a1.y, a1.z, a1.w};
            float xb[8] = {c0.x, c0.y, c0.z, c0.w, c1.x, c1.y, c1.z, c1.w};
            ull t2a[4] = {0, 0, 0, 0}, t2b[4] = {0, 0, 0, 0};
            const float* wb = s_w + (il & 3) * 1280 + n * 128 + dh * 8;
#pragma unroll
            for (int p = 0; p < P_; p++) {
                ull xpa = pack2(xa[p], xa[p]);
                ull xpb = pack2(xb[p], xb[p]);
                ulonglong2 w0 = *(const ulonglong2*)(wb + p * 16);
                ulonglong2 w1 = *(const ulonglong2*)(wb + p * 16 + 4);
                t2a[0] = ffma2(xpa, w0.x, t2a[0]); t2a[1] = ffma2(xpa, w0.y, t2a[1]);
                t2a[2] = ffma2(xpa, w1.x, t2a[2]); t2a[3] = ffma2(xpa, w1.y, t2a[3]);
                t2b[0] = ffma2(xpb, w0.x, t2b[0]); t2b[1] = ffma2(xpb, w0.y, t2b[1]);
                t2b[2] = ffma2(xpb, w1.x, t2b[2]); t2b[3] = ffma2(xpb, w1.y, t2b[3]);
            }
#pragma unroll
            for (int j = 0; j < 4; j++) {
                sa[j] = fadd2(sa[j], t2a[j]);
                sb[j] = fadd2(sb[j], t2b[j]);
            }
        }
        cp_wait0();
        __syncthreads();
    }
    if (ip < ni) {   // odd tail (ni = 27): W(ip) staged two pairs ago, still valid
        const int il = ip;
        const float4* xra = sxa + il * 2;
        const float4* xrb = sxb + il * 2;
        float4 a0 = xra[0], a1 = xra[1], c0 = xrb[0], c1 = xrb[1];
        float xa[8] = {a0.x, a0.y, a0.z, a0.w, a1.x, a1.y, a1.z, a1.w};
        float xb[8] = {c0.x, c0.y, c0.z, c0.w, c1.x, c1.y, c1.z, c1.w};
        ull t2a[4] = {0, 0, 0, 0}, t2b[4] = {0, 0, 0, 0};
        const float* wb = s_w + (il & 3) * 1280 + n * 128 + dh * 8;
#pragma unroll
        for (int p = 0; p < P_; p++) {
            ull xpa = pack2(xa[p], xa[p]);
            ull xpb = pack2(xb[p], xb[p]);
            ulonglong2 w0 = *(const ulonglong2*)(wb + p * 16);
            ulonglong2 w1 = *(const ulonglong2*)(wb + p * 16 + 4);
            t2a[0] = ffma2(xpa, w0.x, t2a[0]); t2a[1] = ffma2(xpa, w0.y, t2a[1]);
            t2a[2] = ffma2(xpa, w1.x, t2a[2]); t2a[3] = ffma2(xpa, w1.y, t2a[3]);
            t2b[0] = ffma2(xpb, w0.x, t2b[0]); t2b[1] = ffma2(xpb, w0.y, t2b[1]);
            t2b[2] = ffma2(xpb, w1.x, t2b[2]); t2b[3] = ffma2(xpb, w1.y, t2b[3]);
        }
#pragma unroll
        for (int j = 0; j < 4; j++) {
            sa[j] = fadd2(sa[j], t2a[j]);
            sb[j] = fadd2(sb[j], t2b[j]);
        }
    }

    // replicated vector atomics (k = 0.1)
    {
        float2 a0 = unpack2(sa[0]), a1 = unpack2(sa[1]);
        float2 a2 = unpack2(sa[2]), a3 = unpack2(sa[3]);
        float2 c0 = unpack2(sb[0]), c1 = unpack2(sb[1]);
        float2 c2 = unpack2(sb[2]), c3 = unpack2(sb[3]);
        float* base = &g_srep[0][cb & (NREP - 1)][0];
        float4* s1 = (float4*)(base + b1 * ND_ + n * D_ + dh * 8);
        float4* s2 = (float4*)(base + b2 * ND_ + n * D_ + dh * 8);
        atomicAdd(s1,     make_float4(a0.x * .1f, a0.y * .1f, a1.x * .1f, a1.y * .1f));
        atomicAdd(s1 + 1, make_float4(a2.x * .1f, a2.y * .1f, a3.x * .1f, a3.y * .1f));
        atomicAdd(s2,     make_float4(c0.x * .1f, c0.y * .1f, c1.x * .1f, c1.y * .1f));
        atomicAdd(s2 + 1, make_float4(c2.x * .1f, c2.y * .1f, c3.x * .1f, c3.y * .1f));
    }
}

// ============================================================================
// pass1/2: unchanged from R13
// ============================================================================
template <int PASS>
__global__ __launch_bounds__(THREADS, 2) void k_pass(const float* __restrict__ X,
                                                     const float* __restrict__ W) {
    extern __shared__ float smem[];
    float* s_x = smem;
    float* s_w = smem + SX_SZ;
    float* s_e = s_w + SW_SZ;

    const int tid = threadIdx.x;
    const int n   = tid >> 5;
    const int l   = tid & 31;
    const int bb  = l & 15;
    const int dh  = l >> 4;
    const int cb  = blockIdx.x;
    const int bh  = blockIdx.y;
    int i0, ni;
    if (cb < 100) { i0 = cb * 28; ni = 28; }
    else          { i0 = 2800 + (cb - 100) * 27; ni = 27; }
    const int b1 = bh * 32 + bb;
    const int b2 = b1 + 16;

    {
        int nr = ni * 8;
        for (int idx = tid; idx < 32 * nr; idx += THREADS) {
            int lb = idx / nr;
            int r  = idx - lb * nr;
            s_x[lb * SX_STRIDE + r] = X[(size_t)(bh * 32 + lb) * (I_ * P_) + i0 * P_ + r];
        }
    }
    *(float4*)(s_w + tid * 4) = *(const float4*)(W + (size_t)i0 * 1280 + tid * 4);

    ull v2a[4], v2b[4];
    {
        const float4* va = (const float4*)(g_v + b1 * ND_ + n * D_ + dh * 8);
        const float4* vb = (const float4*)(g_v + b2 * ND_ + n * D_ + dh * 8);
        float4 a0 = va[0], a1 = va[1], c0 = vb[0], c1 = vb[1];
        v2a[0] = pack2(a0.x * L2E, a0.y * L2E); v2a[1] = pack2(a0.z * L2E, a0.w * L2E);
        v2a[2] = pack2(a1.x * L2E, a1.y * L2E); v2a[3] = pack2(a1.z * L2E, a1.w * L2E);
        v2b[0] = pack2(c0.x * L2E, c0.y * L2E); v2b[1] = pack2(c0.z * L2E, c0.w * L2E);
        v2b[2] = pack2(c1.x * L2E, c1.y * L2E); v2b[3] = pack2(c1.z * L2E, c1.w * L2E);
    }
    __syncthreads();

    ull t2a[4], t2b[4], sa[4], sb[4];
#pragma unroll
    for (int j = 0; j < 4; j++) { sa[j] = 0ULL; sb[j] = 0ULL; }
    float e1p = 0.f, e2p = 0.f;

    const float* wsrc = W + (size_t)(i0 + 1) * 1280 + tid * 4;
    float* gbp = g_blog + (size_t)i0 * 640 + n * 64 + bh * 32 + l;
    const float4* sxa = (const float4*)(s_x + bb * SX_STRIDE);
    const float4* sxb = (const float4*)(s_x + (bb + 16) * SX_STRIDE);

#pragma unroll 2
    for (int il = 0; il < ni; il++) {
        const int cur = il & 1;
        const bool wok = (il + 1 < ni);

        float4 wpf;
        if (wok) wpf = *(const float4*)(wsrc);
        float gb1 = 0.f, gb2 = 0.f;
        if (PASS == 2) {
            float go = *gbp;
            float gt = __shfl_xor_sync(0xffffffffu, go, 16);
            gb1 = dh ? gt : go;
            gb2 = dh ? go : gt;
        }

        if (il > 0) {
            const float* se = s_e + (1 - cur) * 352 + l * 11;
            float Z = ((se[0] + se[1]) + (se[2] + se[3])) +
                      ((se[4] + se[5]) + (se[6] + se[7])) + (se[8] + se[9]);
            float Zo = __shfl_xor_sync(0xffffffffu, Z, 16);
            float Z1 = dh ? Zo : Z;
            float Z2 = dh ? Z : Zo;
            float c1 = __fdividef(e1p, Z1);
            float c2 = __fdividef(e2p, Z2);
            ull cp1 = pack2(c1, c1), cp2 = pack2(c2, c2);
#pragma unroll
            for (int j = 0; j < 4; j++) {
                sa[j] = ffma2(cp1, t2a[j], sa[j]);
                sb[j] = ffma2(cp2, t2b[j], sb[j]);
            }
        }

        float xa[8], xb[8];
        {
            const float4* xra = sxa + il * 2;
            const float4* xrb = sxb + il * 2;
            float4 a0 = xra[0], a1 = xra[1], c0 = xrb[0], c1 = xrb[1];
            xa[0] = a0.x; xa[1] = a0.y; xa[2] = a0.z; xa[3] = a0.w;
            xa[4] = a1.x; xa[5] = a1.y; xa[6] = a1.z; xa[7] = a1.w;
            xb[0] = c0.x; xb[1] = c0.y; xb[2] = c0.z; xb[3] = c0.w;
            xb[4] = c1.x; xb[5] = c1.y; xb[6] = c1.z; xb[7] = c1.w;
        }

#pragma unroll
        for (int j = 0; j < 4; j++) { t2a[j] = 0ULL; t2b[j] = 0ULL; }
        {
            const float* wb = s_w + cur * 1280 + n * 128 + dh * 8;
#pragma unroll
            for (int p = 0; p < P_; p++) {
                ull xpa = pack2(xa[p], xa[p]);
                ull xpb = pack2(xb[p], xb[p]);
                ulonglong2 w0 = *(const ulonglong2*)(wb + p * 16);
                ulonglong2 w1 = *(const ulonglong2*)(wb + p * 16 + 4);
                t2a[0] = ffma2(xpa, w0.x, t2a[0]); t2a[1] = ffma2(xpa, w0.y, t2a[1]);
                t2a[2] = ffma2(xpa, w1.x, t2a[2]); t2a[3] = ffma2(xpa, w1.y, t2a[3]);
                t2b[0] = ffma2(xpb, w0.x, t2b[0]); t2b[1] = ffma2(xpb, w0.y, t2b[1]);
                t2b[2] = ffma2(xpb, w1.x, t2b[2]); t2b[3] = ffma2(xpb, w1.y, t2b[3]);
            }
        }

        {
            ull aa = 0ULL, ab = 0ULL;
#pragma unroll
            for (int j = 0; j < 4; j++) {
                aa = ffma2(t2a[j], v2a[j], aa);
                ab = ffma2(t2b[j], v2b[j], ab);
            }
            float2 fa = unpack2(aa); float pa = fa.x + fa.y;
            float2 fb = unpack2(ab); float pb = fb.x + fb.y;
            float pao = __shfl_xor_sync(0xffffffffu, pa, 16);
            float pbo = __shfl_xor_sync(0xffffffffu, pb, 16);
            float bn1 = pa + pao + gb1;
            float bn2 = pb + pbo + gb2;
            if (PASS == 1) *gbp = dh ? bn2 : bn1;
            e1p = fast_ex2(bn1);
            e2p = fast_ex2(bn2);
            s_e[cur * 352 + l * 11 + n] = dh ? e2p : e1p;
        }
        gbp += 640;
        if (wok) {
            *(float4*)(s_w + (1 - cur) * 1280 + tid * 4) = wpf;
            wsrc += 1280;
        }

        __syncthreads();
    }

    {
        const int prev = (ni - 1) & 1;
        const float* se = s_e + prev * 352 + l * 11;
        float Z = ((se[0] + se[1]) + (se[2] + se[3])) +
                  ((se[4] + se[5]) + (se[6] + se[7])) + (se[8] + se[9]);
        float Zo = __shfl_xor_sync(0xffffffffu, Z, 16);
        float Z1 = dh ? Zo : Z;
        float Z2 = dh ? Z : Zo;
        float c1 = __fdividef(e1p, Z1);
        float c2 = __fdividef(e2p, Z2);
        ull cp1 = pack2(c1, c1), cp2 = pack2(c2, c2);
#pragma unroll
        for (int j = 0; j < 4; j++) {
            sa[j] = ffma2(cp1, t2a[j], sa[j]);
            sb[j] = ffma2(cp2, t2b[j], sb[j]);
        }
    }

    {
        float2 a0 = unpack2(sa[0]), a1 = unpack2(sa[1]);
        float2 a2 = unpack2(sa[2]), a3 = unpack2(sa[3]);
        float2 c0 = unpack2(sb[0]), c1 = unpack2(sb[1]);
        float2 c2 = unpack2(sb[2]), c3 = unpack2(sb[3]);
        float* base = &g_srep[PASS][cb & (NREP - 1)][0];
        float4* s1 = (float4*)(base + b1 * ND_ + n * D_ + dh * 8);
        float4* s2 = (float4*)(base + b2 * ND_ + n * D_ + dh * 8);
        atomicAdd(s1,     make_float4(a0.x, a0.y, a1.x, a1.y));
        atomicAdd(s1 + 1, make_float4(a2.x, a2.y, a3.x, a3.y));
        atomicAdd(s2,     make_float4(c0.x, c0.y, c1.x, c1.y));
        atomicAdd(s2 + 1, make_float4(c2.x, c2.y, c3.x, c3.y));
    }
}

// Depth-16 fixed-order replica sum + elementwise squash. Grid 40 x 256.
template <int PSET, bool FINAL>
__global__ __launch_bounds__(256) void k_squash(float* __restrict__ dout) {
    int idx = blockIdx.x * 256 + threadIdx.x;
    if (idx < OUT_) {
        const float* p = &g_srep[PSET][0][0] + idx;
        float a0 = 0.f, a1 = 0.f, a2 = 0.f, a3 = 0.f;
#pragma unroll
        for (int r = 0; r < NREP; r += 4) {
            a0 += p[(r + 0) * OUT_];
            a1 += p[(r + 1) * OUT_];
            a2 += p[(r + 2) * OUT_];
            a3 += p[(r + 3) * OUT_];
        }
        float s = (a0 + a1) + (a2 + a3);
        float sq = s * s;
        float scale = sq / ((1.f + sq) * sqrtf(sq + 1e-7f));
        float v = scale * s;
        if (FINAL) dout[idx] = v;
        else       g_v[idx] = v;
    }
}

extern "C" void kernel_launch(void* const* d_in, const int* in_sizes, int n_in,
                              void* d_out, int out_size) {
    const float* X = (const float*)d_in[0];
    const float* W = (const float*)d_in[1];
    if (n_in >= 2 && in_sizes[0] != B_ * I_ * P_) {
        const float* tmp = X; X = W; W = tmp;
    }

    cudaFuncSetAttribute(k_pass0, cudaFuncAttributeMaxDynamicSharedMemorySize, SMEM0_BYTES);

    dim3 gp(148, 2);
    k_pad<<<1920, 256>>>();
    k_pass0<<<gp, THREADS, SMEM0_BYTES>>>(X, W);
    k_squash<0, false><<<40, 256>>>(nullptr);
    k_pass<1><<<gp, THREADS, SMEM_BYTES>>>(X, W);
    k_squash<1, false><<<40, 256>>>(nullptr);
    k_pass<2><<<gp, THREADS, SMEM_BYTES>>>(X, W);
    k_squash<2, true><<<40, 256>>>((float*)d_out);
}

// round 15
// speedup vs baseline: 1.0818x; 1.0818x over previous
#include <cuda_runtime.h>

// DigitCaps dynamic routing, GB300 sm_103a — R15.
// B=64, I=4096, Din=8, N=10, D=16, 3 routing iterations.
//
// R15 = R13 exactly (best measured 104.96: R6 k_pass fabric + 16-replica
// atomics + k_squash), minus the 2MB k_pad zeroing pass:
//  - __device__ globals start zeroed; each k_squash<PSET> re-zeroes its own
//    replica set after the fixed-order read -> graph stays replay-invariant
//  - R14 pass0 quad-buffer specialization reverted (regressed +6us)
//  - 1-thread pad kernel kept only to pin ncu -s 5 onto k_pass<2>

#define B_ 64
#define I_ 4096
#define P_ 8
#define N_ 10
#define D_ 16
#define ND_ 160
#define THREADS 320              // 32 b x 10 n, lane = 16bb x 2dh, BTILE=2
#define OUT_ (B_ * ND_)          // 10240
#define NREP 16
#define L2E 1.4426950408889634f

#define SX_STRIDE 236
#define SX_SZ (32 * SX_STRIDE)   // 7552 floats
#define SW_SZ (2 * 1280)
#define SE_SZ (2 * 352)
#define SMEM_BYTES ((SX_SZ + SW_SZ + SE_SZ) * 4)   // 43,264 B (< 48K default)

__device__ float g_srep[3][NREP][OUT_];         // replicated atomic accumulators (zero-init)
__device__ float g_blog[(size_t)I_ * 640];      // log2-domain logits [i][n*64+bh*32+l]
__device__ float g_v[OUT_];                     // squashed v
__device__ float g_padsink;

typedef unsigned long long ull;

static __device__ __forceinline__ ull pack2(float a, float b) {
    ull r; asm("mov.b64 %0, {%1,%2};" : "=l"(r) : "f"(a), "f"(b)); return r;
}
static __device__ __forceinline__ float2 unpack2(ull v) {
    float2 r; asm("mov.b64 {%0,%1}, %2;" : "=f"(r.x), "=f"(r.y) : "l"(v)); return r;
}
static __device__ __forceinline__ ull ffma2(ull a, ull b, ull c) {
    ull d; asm("fma.rn.f32x2 %0, %1, %2, %3;" : "=l"(d) : "l"(a), "l"(b), "l"(c)); return d;
}
static __device__ __forceinline__ ull fadd2(ull a, ull b) {
    ull d; asm("add.rn.f32x2 %0, %1, %2;" : "=l"(d) : "l"(a), "l"(b)); return d;
}
static __device__ __forceinline__ float fast_ex2(float x) {
    float r; asm("ex2.approx.f32 %0, %1;" : "=f"(r) : "f"(x)); return r;
}

// keeps ncu -s 5 -c 1 landing on k_pass<2>; negligible work
__global__ void k_pad() { g_padsink = 0.0f; }

template <int PASS>
__global__ __launch_bounds__(THREADS, 2) void k_pass(const float* __restrict__ X,
                                                     const float* __restrict__ W) {
    extern __shared__ float smem[];
    float* s_x = smem;                 // [lb][r] stride SX_STRIDE
    float* s_w = smem + SX_SZ;         // 2 x 1280
    float* s_e = s_w + SW_SZ;          // 2 x (32*11)

    const int tid = threadIdx.x;
    const int n   = tid >> 5;          // warp id = n
    const int l   = tid & 31;          // lane
    const int bb  = l & 15;
    const int dh  = l >> 4;            // d-half
    const int cb  = blockIdx.x;        // i-chunk
    const int bh  = blockIdx.y;        // batch half
    int i0, ni;
    if (cb < 100) { i0 = cb * 28; ni = 28; }
    else          { i0 = 2800 + (cb - 100) * 27; ni = 27; }
    const int b1 = bh * 32 + bb;
    const int b2 = b1 + 16;

    // ---- stage x: rows = 32 local batches, ni*8 floats each
    {
        int nr = ni * 8;
        for (int idx = tid; idx < 32 * nr; idx += THREADS) {
            int lb = idx / nr;
            int r  = idx - lb * nr;
            s_x[lb * SX_STRIDE + r] = X[(size_t)(bh * 32 + lb) * (I_ * P_) + i0 * P_ + r];
        }
    }
    // ---- stage W(0)
    *(float4*)(s_w + tid * 4) = *(const float4*)(W + (size_t)i0 * 1280 + tid * 4);

    // ---- v (log2-scaled) for both batches, this thread's d-half
    ull v2a[4], v2b[4];
    if (PASS > 0) {
        const float4* va = (const float4*)(g_v + b1 * ND_ + n * D_ + dh * 8);
        const float4* vb = (const float4*)(g_v + b2 * ND_ + n * D_ + dh * 8);
        float4 a0 = va[0], a1 = va[1], c0 = vb[0], c1 = vb[1];
        v2a[0] = pack2(a0.x * L2E, a0.y * L2E); v2a[1] = pack2(a0.z * L2E, a0.w * L2E);
        v2a[2] = pack2(a1.x * L2E, a1.y * L2E); v2a[3] = pack2(a1.z * L2E, a1.w * L2E);
        v2b[0] = pack2(c0.x * L2E, c0.y * L2E); v2b[1] = pack2(c0.z * L2E, c0.w * L2E);
        v2b[2] = pack2(c1.x * L2E, c1.y * L2E); v2b[3] = pack2(c1.z * L2E, c1.w * L2E);
    }
    __syncthreads();

    ull t2a[4], t2b[4], sa[4], sb[4];
#pragma unroll
    for (int j = 0; j < 4; j++) { sa[j] = 0ULL; sb[j] = 0ULL; }
    float e1p = 0.f, e2p = 0.f;

    const float* wsrc = W + (size_t)(i0 + 1) * 1280 + tid * 4;
    float* gbp = g_blog + (size_t)i0 * 640 + n * 64 + bh * 32 + l;
    const float4* sxa = (const float4*)(s_x + bb * SX_STRIDE);
    const float4* sxb = (const float4*)(s_x + (bb + 16) * SX_STRIDE);

#pragma unroll 2
    for (int il = 0; il < ni; il++) {
        const int cur = il & 1;
        const bool wok = (il + 1 < ni);

        // prefetch W(il+1), (pass2) prior logit
        float4 wpf;
        if (wok) wpf = *(const float4*)(wsrc);
        float gb1 = 0.f, gb2 = 0.f;
        if (PASS == 2) {
            float go = *gbp;
            float gt = __shfl_xor_sync(0xffffffffu, go, 16);
            gb1 = dh ? gt : go;
            gb2 = dh ? go : gt;
        }

        // ---- consume stage il-1 (t2 holds t(il-1); e(il-1) in s_e[1-cur])
        if (il > 0) {
            if (PASS > 0) {
                const float* se = s_e + (1 - cur) * 352 + l * 11;
                float Z = ((se[0] + se[1]) + (se[2] + se[3])) +
                          ((se[4] + se[5]) + (se[6] + se[7])) + (se[8] + se[9]);
                float Zo = __shfl_xor_sync(0xffffffffu, Z, 16);
                float Z1 = dh ? Zo : Z;
                float Z2 = dh ? Z : Zo;
                float c1 = __fdividef(e1p, Z1);
                float c2 = __fdividef(e2p, Z2);
                ull cp1 = pack2(c1, c1), cp2 = pack2(c2, c2);
#pragma unroll
                for (int j = 0; j < 4; j++) {
                    sa[j] = ffma2(cp1, t2a[j], sa[j]);
                    sb[j] = ffma2(cp2, t2b[j], sb[j]);
                }
            } else {
#pragma unroll
                for (int j = 0; j < 4; j++) {
                    sa[j] = fadd2(sa[j], t2a[j]);
                    sb[j] = fadd2(sb[j], t2b[j]);
                }
            }
        }

        // ---- x(il): 2 x LDS.128 per batch
        float xa[8], xb[8];
        {
            const float4* xra = sxa + il * 2;
            const float4* xrb = sxb + il * 2;
            float4 a0 = xra[0], a1 = xra[1], c0 = xrb[0], c1 = xrb[1];
            xa[0] = a0.x; xa[1] = a0.y; xa[2] = a0.z; xa[3] = a0.w;
            xa[4] = a1.x; xa[5] = a1.y; xa[6] = a1.z; xa[7] = a1.w;
            xb[0] = c0.x; xb[1] = c0.y; xb[2] = c0.z; xb[3] = c0.w;
            xb[4] = c1.x; xb[5] = c1.y; xb[6] = c1.z; xb[7] = c1.w;
        }

        // ---- t(il) = u[b, i, n, d-half] for both batches
#pragma unroll
        for (int j = 0; j < 4; j++) { t2a[j] = 0ULL; t2b[j] = 0ULL; }
        {
            const float* wb = s_w + cur * 1280 + n * 128 + dh * 8;
#pragma unroll
            for (int p = 0; p < P_; p++) {
                ull xpa = pack2(xa[p], xa[p]);
                ull xpb = pack2(xb[p], xb[p]);
                ulonglong2 w0 = *(const ulonglong2*)(wb + p * 16);
                ulonglong2 w1 = *(const ulonglong2*)(wb + p * 16 + 4);
                t2a[0] = ffma2(xpa, w0.x, t2a[0]); t2a[1] = ffma2(xpa, w0.y, t2a[1]);
                t2a[2] = ffma2(xpa, w1.x, t2a[2]); t2a[3] = ffma2(xpa, w1.y, t2a[3]);
                t2b[0] = ffma2(xpb, w0.x, t2b[0]); t2b[1] = ffma2(xpb, w0.y, t2b[1]);
                t2b[2] = ffma2(xpb, w1.x, t2b[2]); t2b[3] = ffma2(xpb, w1.y, t2b[3]);
            }
        }

        // ---- agreement + exp (log2 domain)
        if (PASS > 0) {
            ull aa = 0ULL, ab = 0ULL;
#pragma unroll
            for (int j = 0; j < 4; j++) {
                aa = ffma2(t2a[j], v2a[j], aa);
                ab = ffma2(t2b[j], v2b[j], ab);
            }
            float2 fa = unpack2(aa); float pa = fa.x + fa.y;
            float2 fb = unpack2(ab); float pb = fb.x + fb.y;
            float pao = __shfl_xor_sync(0xffffffffu, pa, 16);
            float pbo = __shfl_xor_sync(0xffffffffu, pb, 16);
            float bn1 = pa + pao + gb1;
            float bn2 = pb + pbo + gb2;
            if (PASS == 1) *gbp = dh ? bn2 : bn1;   // PASS2 is last: no store
            e1p = fast_ex2(bn1);
            e2p = fast_ex2(bn2);
            s_e[cur * 352 + l * 11 + n] = dh ? e2p : e1p;
        }
        if (PASS > 0) gbp += 640;
        if (wok) {
            *(float4*)(s_w + (1 - cur) * 1280 + tid * 4) = wpf;
            wsrc += 1280;
        }

        __syncthreads();
    }

    // ---- epilogue: consume last stage
    {
        const int prev = (ni - 1) & 1;
        if (PASS > 0) {
            const float* se = s_e + prev * 352 + l * 11;
            float Z = ((se[0] + se[1]) + (se[2] + se[3])) +
                      ((se[4] + se[5]) + (se[6] + se[7])) + (se[8] + se[9]);
            float Zo = __shfl_xor_sync(0xffffffffu, Z, 16);
            float Z1 = dh ? Zo : Z;
            float Z2 = dh ? Z : Zo;
            float c1 = __fdividef(e1p, Z1);
            float c2 = __fdividef(e2p, Z2);
            ull cp1 = pack2(c1, c1), cp2 = pack2(c2, c2);
#pragma unroll
            for (int j = 0; j < 4; j++) {
                sa[j] = ffma2(cp1, t2a[j], sa[j]);
                sb[j] = ffma2(cp2, t2b[j], sb[j]);
            }
        } else {
#pragma unroll
            for (int j = 0; j < 4; j++) {
                sa[j] = fadd2(sa[j], t2a[j]);
                sb[j] = fadd2(sb[j], t2b[j]);
            }
        }
    }

    // ---- replicated vector-atomic accumulation (depth ~19 per address)
    {
        float2 a0 = unpack2(sa[0]), a1 = unpack2(sa[1]);
        float2 a2 = unpack2(sa[2]), a3 = unpack2(sa[3]);
        float2 c0 = unpack2(sb[0]), c1 = unpack2(sb[1]);
        float2 c2 = unpack2(sb[2]), c3 = unpack2(sb[3]);
        float k = (PASS == 0) ? 0.1f : 1.0f;
        float* base = &g_srep[PASS][cb & (NREP - 1)][0];
        float4* s1 = (float4*)(base + b1 * ND_ + n * D_ + dh * 8);
        float4* s2 = (float4*)(base + b2 * ND_ + n * D_ + dh * 8);
        atomicAdd(s1,     make_float4(a0.x * k, a0.y * k, a1.x * k, a1.y * k));
        atomicAdd(s1 + 1, make_float4(a2.x * k, a2.y * k, a3.x * k, a3.y * k));
        atomicAdd(s2,     make_float4(c0.x * k, c0.y * k, c1.x * k, c1.y * k));
        atomicAdd(s2 + 1, make_float4(c2.x * k, c2.y * k, c3.x * k, c3.y * k));
    }
}

// Depth-16 fixed-order replica sum + squash; re-zeroes its replica set so the
// next graph replay starts clean (globals are zero-initialized at load for
// the very first run). Grid 40 x 256.
template <int PSET, bool FINAL>
__global__ __launch_bounds__(256) void k_squash(float* __restrict__ dout) {
    int idx = blockIdx.x * 256 + threadIdx.x;
    if (idx < OUT_) {
        float* p = &g_srep[PSET][0][0] + idx;
        float a0 = 0.f, a1 = 0.f, a2 = 0.f, a3 = 0.f;
#pragma unroll
        for (int r = 0; r < NREP; r += 4) {
            a0 += p[(r + 0) * OUT_];
            a1 += p[(r + 1) * OUT_];
            a2 += p[(r + 2) * OUT_];
            a3 += p[(r + 3) * OUT_];
        }
#pragma unroll
        for (int r = 0; r < NREP; r++) p[r * OUT_] = 0.0f;
        float s = (a0 + a1) + (a2 + a3);
        float sq = s * s;
        float scale = sq / ((1.f + sq) * sqrtf(sq + 1e-7f));
        float v = scale * s;
        if (FINAL) dout[idx] = v;
        else       g_v[idx] = v;
    }
}

extern "C" void kernel_launch(void* const* d_in, const int* in_sizes, int n_in,
                              void* d_out, int out_size) {
    const float* X = (const float*)d_in[0];
    const float* W = (const float*)d_in[1];
    if (n_in >= 2 && in_sizes[0] != B_ * I_ * P_) {
        const float* tmp = X; X = W; W = tmp;
    }

    dim3 gp(148, 2);
    k_pad<<<1, 1>>>();                                   // ncu -s 5 -> k_pass<2>
    k_pass<0><<<gp, THREADS, SMEM_BYTES>>>(X, W);
    k_squash<0, false><<<40, 256>>>(nullptr);
    k_pass<1><<<gp, THREADS, SMEM_BYTES>>>(X, W);
    k_squash<1, false><<<40, 256>>>(nullptr);
    k_pass<2><<<gp, THREADS, SMEM_BYTES>>>(X, W);
    k_squash<2, true><<<40, 256>>>((float*)d_out);
}

// round 16
// speedup vs baseline: 1.1013x; 1.0180x over previous
#include <cuda_runtime.h>

// DigitCaps dynamic routing, GB300 sm_103a — R16: single persistent kernel.
// B=64, I=4096, Din=8, N=10, D=16, 3 routing iterations.
//
// R16 = R15 (102.9 WIN) fused into ONE kernel with hand-rolled grid barriers:
//  - grid 296 = 148 SMs x 2 blocks (launch_bounds(320,2) guarantees
//    co-residency) -> monotonic-counter grid barrier is safe
//  - x staged into smem ONCE (was 3x); 5 launch boundaries eliminated;
//    squash inline on 32 blocks between barriers
//  - within-launch L1 not flushed: g_v / g_srep cross-SM reads via __ldcg;
//    g_blog is same-block (own-L1 coherent); threadfence at barriers
//  - end protocol: g_done counts finished blocks; last one resets the
//    barrier counter (no spinner can still be watching it) -> replay-safe

#define B_ 64
#define I_ 4096
#define P_ 8
#define N_ 10
#define D_ 16
#define ND_ 160
#define THREADS 320              // 32 b x 10 n, lane = 16bb x 2dh, BTILE=2
#define OUT_ (B_ * ND_)          // 10240
#define NREP 16
#define NBLK 296
#define L2E 1.4426950408889634f

#define SX_STRIDE 236
#define SX_SZ (32 * SX_STRIDE)   // 7552 floats
#define SW_SZ (2 * 1280)
#define SE_SZ (2 * 352)
#define SMEM_BYTES ((SX_SZ + SW_SZ + SE_SZ) * 4)   // 43,264 B (2 blocks/SM ok)

__device__ float g_srep[3][NREP][OUT_];         // replicated atomic accumulators (zero-init)
__device__ float g_blog[(size_t)I_ * 640];      // log2-domain logits (same-block use)
__device__ float g_v[OUT_];                     // squashed v
__device__ unsigned g_gc;                       // grid-barrier counter (zero-init)
__device__ unsigned g_done;                     // end-protocol counter

typedef unsigned long long ull;

static __device__ __forceinline__ ull pack2(float a, float b) {
    ull r; asm("mov.b64 %0, {%1,%2};" : "=l"(r) : "f"(a), "f"(b)); return r;
}
static __device__ __forceinline__ float2 unpack2(ull v) {
    float2 r; asm("mov.b64 {%0,%1}, %2;" : "=f"(r.x), "=f"(r.y) : "l"(v)); return r;
}
static __device__ __forceinline__ ull ffma2(ull a, ull b, ull c) {
    ull d; asm("fma.rn.f32x2 %0, %1, %2, %3;" : "=l"(d) : "l"(a), "l"(b), "l"(c)); return d;
}
static __device__ __forceinline__ ull fadd2(ull a, ull b) {
    ull d; asm("add.rn.f32x2 %0, %1, %2;" : "=l"(d) : "l"(a), "l"(b)); return d;
}
static __device__ __forceinline__ float fast_ex2(float x) {
    float r; asm("ex2.approx.f32 %0, %1;" : "=f"(r) : "f"(x)); return r;
}

// Monotonic grid barrier: all NBLK blocks arrive; spinners exit on count>=goal.
// Counter is reset only by the end protocol (after every block passed the
// final barrier), so no spinner can observe the reset.
static __device__ __forceinline__ void grid_bar(unsigned goal) {
    __syncthreads();
    if (threadIdx.x == 0) {
        __threadfence();
        atomicAdd(&g_gc, 1u);
        while (*(volatile unsigned*)&g_gc < goal) { }
        __threadfence();
    }
    __syncthreads();
}

// One routing pass over this block's i-chunk (R15 fabric, unchanged math).
template <int PASS>
static __device__ __forceinline__ void run_pass(
    const float* __restrict__ W,
    const float* s_x, float* s_w, float* s_e,
    int i0, int ni, int tid, int n, int l, int bb, int dh,
    int cb, int b1, int b2)
{
    // stage W(0)
    *(float4*)(s_w + tid * 4) = *(const float4*)(W + (size_t)i0 * 1280 + tid * 4);

    // v (log2-scaled), L2-coherent loads (L1 may hold stale lines in-launch)
    ull v2a[4], v2b[4];
    if (PASS > 0) {
        float4 a0 = __ldcg((const float4*)(g_v + b1 * ND_ + n * D_ + dh * 8));
        float4 a1 = __ldcg((const float4*)(g_v + b1 * ND_ + n * D_ + dh * 8) + 1);
        float4 c0 = __ldcg((const float4*)(g_v + b2 * ND_ + n * D_ + dh * 8));
        float4 c1 = __ldcg((const float4*)(g_v + b2 * ND_ + n * D_ + dh * 8) + 1);
        v2a[0] = pack2(a0.x * L2E, a0.y * L2E); v2a[1] = pack2(a0.z * L2E, a0.w * L2E);
        v2a[2] = pack2(a1.x * L2E, a1.y * L2E); v2a[3] = pack2(a1.z * L2E, a1.w * L2E);
        v2b[0] = pack2(c0.x * L2E, c0.y * L2E); v2b[1] = pack2(c0.z * L2E, c0.w * L2E);
        v2b[2] = pack2(c1.x * L2E, c1.y * L2E); v2b[3] = pack2(c1.z * L2E, c1.w * L2E);
    }
    __syncthreads();

    ull t2a[4], t2b[4], sa[4], sb[4];
#pragma unroll
    for (int j = 0; j < 4; j++) { sa[j] = 0ULL; sb[j] = 0ULL; }
    float e1p = 0.f, e2p = 0.f;

    const float* wsrc = W + (size_t)(i0 + 1) * 1280 + tid * 4;
    float* gbp = g_blog + (size_t)i0 * 640 + n * 64 + (b1 & 32) * 10 + l;
    // (b1&32)*10 == bh*320; keep identical addressing to R15: bh*32 within 640
    // R15 used: i0*640 + n*64 + bh*32 + l; recompute exactly:
    gbp = g_blog + (size_t)i0 * 640 + n * 64 + (b1 - bb) + l;   // bh*32 = b1 - bb

    const float4* sxa = (const float4*)(s_x + bb * SX_STRIDE);
    const float4* sxb = (const float4*)(s_x + (bb + 16) * SX_STRIDE);

#pragma unroll 2
    for (int il = 0; il < ni; il++) {
        const int cur = il & 1;
        const bool wok = (il + 1 < ni);

        float4 wpf;
        if (wok) wpf = *(const float4*)(wsrc);
        float gb1 = 0.f, gb2 = 0.f;
        if (PASS == 2) {
            float go = *gbp;                       // same-block write in pass1
            float gt = __shfl_xor_sync(0xffffffffu, go, 16);
            gb1 = dh ? gt : go;
            gb2 = dh ? go : gt;
        }

        if (il > 0) {
            if (PASS > 0) {
                const float* se = s_e + (1 - cur) * 352 + l * 11;
                float Z = ((se[0] + se[1]) + (se[2] + se[3])) +
                          ((se[4] + se[5]) + (se[6] + se[7])) + (se[8] + se[9]);
                float Zo = __shfl_xor_sync(0xffffffffu, Z, 16);
                float Z1 = dh ? Zo : Z;
                float Z2 = dh ? Z : Zo;
                float c1 = __fdividef(e1p, Z1);
                float c2 = __fdividef(e2p, Z2);
                ull cp1 = pack2(c1, c1), cp2 = pack2(c2, c2);
#pragma unroll
                for (int j = 0; j < 4; j++) {
                    sa[j] = ffma2(cp1, t2a[j], sa[j]);
                    sb[j] = ffma2(cp2, t2b[j], sb[j]);
                }
            } else {
#pragma unroll
                for (int j = 0; j < 4; j++) {
                    sa[j] = fadd2(sa[j], t2a[j]);
                    sb[j] = fadd2(sb[j], t2b[j]);
                }
            }
        }

        float xa[8], xb[8];
        {
            const float4* xra = sxa + il * 2;
            const float4* xrb = sxb + il * 2;
            float4 a0 = xra[0], a1 = xra[1], c0 = xrb[0], c1 = xrb[1];
            xa[0] = a0.x; xa[1] = a0.y; xa[2] = a0.z; xa[3] = a0.w;
            xa[4] = a1.x; xa[5] = a1.y; xa[6] = a1.z; xa[7] = a1.w;
            xb[0] = c0.x; xb[1] = c0.y; xb[2] = c0.z; xb[3] = c0.w;
            xb[4] = c1.x; xb[5] = c1.y; xb[6] = c1.z; xb[7] = c1.w;
        }

#pragma unroll
        for (int j = 0; j < 4; j++) { t2a[j] = 0ULL; t2b[j] = 0ULL; }
        {
            const float* wb = s_w + cur * 1280 + n * 128 + dh * 8;
#pragma unroll
            for (int p = 0; p < P_; p++) {
                ull xpa = pack2(xa[p], xa[p]);
                ull xpb = pack2(xb[p], xb[p]);
                ulonglong2 w0 = *(const ulonglong2*)(wb + p * 16);
                ulonglong2 w1 = *(const ulonglong2*)(wb + p * 16 + 4);
                t2a[0] = ffma2(xpa, w0.x, t2a[0]); t2a[1] = ffma2(xpa, w0.y, t2a[1]);
                t2a[2] = ffma2(xpa, w1.x, t2a[2]); t2a[3] = ffma2(xpa, w1.y, t2a[3]);
                t2b[0] = ffma2(xpb, w0.x, t2b[0]); t2b[1] = ffma2(xpb, w0.y, t2b[1]);
                t2b[2] = ffma2(xpb, w1.x, t2b[2]); t2b[3] = ffma2(xpb, w1.y, t2b[3]);
            }
        }

        if (PASS > 0) {
            ull aa = 0ULL, ab = 0ULL;
#pragma unroll
            for (int j = 0; j < 4; j++) {
                aa = ffma2(t2a[j], v2a[j], aa);
                ab = ffma2(t2b[j], v2b[j], ab);
            }
            float2 fa = unpack2(aa); float pa = fa.x + fa.y;
            float2 fb = unpack2(ab); float pb = fb.x + fb.y;
            float pao = __shfl_xor_sync(0xffffffffu, pa, 16);
            float pbo = __shfl_xor_sync(0xffffffffu, pb, 16);
            float bn1 = pa + pao + gb1;
            float bn2 = pb + pbo + gb2;
            if (PASS == 1) *gbp = dh ? bn2 : bn1;
            e1p = fast_ex2(bn1);
            e2p = fast_ex2(bn2);
            s_e[cur * 352 + l * 11 + n] = dh ? e2p : e1p;
            gbp += 640;
        }
        if (wok) {
            *(float4*)(s_w + (1 - cur) * 1280 + tid * 4) = wpf;
            wsrc += 1280;
        }

        __syncthreads();
    }

    // epilogue: consume last stage
    {
        const int prev = (ni - 1) & 1;
        if (PASS > 0) {
            const float* se = s_e + prev * 352 + l * 11;
            float Z = ((se[0] + se[1]) + (se[2] + se[3])) +
                      ((se[4] + se[5]) + (se[6] + se[7])) + (se[8] + se[9]);
            float Zo = __shfl_xor_sync(0xffffffffu, Z, 16);
            float Z1 = dh ? Zo : Z;
            float Z2 = dh ? Z : Zo;
            float c1 = __fdividef(e1p, Z1);
            float c2 = __fdividef(e2p, Z2);
            ull cp1 = pack2(c1, c1), cp2 = pack2(c2, c2);
#pragma unroll
            for (int j = 0; j < 4; j++) {
                sa[j] = ffma2(cp1, t2a[j], sa[j]);
                sb[j] = ffma2(cp2, t2b[j], sb[j]);
            }
        } else {
#pragma unroll
            for (int j = 0; j < 4; j++) {
                sa[j] = fadd2(sa[j], t2a[j]);
                sb[j] = fadd2(sb[j], t2b[j]);
            }
        }
    }

    // replicated vector atomics (depth ~19 per address)
    {
        float2 a0 = unpack2(sa[0]), a1 = unpack2(sa[1]);
        float2 a2 = unpack2(sa[2]), a3 = unpack2(sa[3]);
        float2 c0 = unpack2(sb[0]), c1 = unpack2(sb[1]);
        float2 c2 = unpack2(sb[2]), c3 = unpack2(sb[3]);
        float k = (PASS == 0) ? 0.1f : 1.0f;
        float* base = &g_srep[PASS][cb & (NREP - 1)][0];
        float4* s1 = (float4*)(base + b1 * ND_ + n * D_ + dh * 8);
        float4* s2 = (float4*)(base + b2 * ND_ + n * D_ + dh * 8);
        atomicAdd(s1,     make_float4(a0.x * k, a0.y * k, a1.x * k, a1.y * k));
        atomicAdd(s1 + 1, make_float4(a2.x * k, a2.y * k, a3.x * k, a3.y * k));
        atomicAdd(s2,     make_float4(c0.x * k, c0.y * k, c1.x * k, c1.y * k));
        atomicAdd(s2 + 1, make_float4(c2.x * k, c2.y * k, c3.x * k, c3.y * k));
    }
}

// Inline squash (32 blocks x 320 threads cover 10240 outputs): depth-16
// fixed-order __ldcg sum, re-zero replica set, squash, store.
static __device__ __forceinline__ void do_squash(int pset, float* __restrict__ dst,
                                                 int fb, int tid) {
    int idx = fb * THREADS + tid;
    float* p = &g_srep[0][0][0] + (size_t)pset * (NREP * OUT_) + idx;
    float a0 = 0.f, a1 = 0.f, a2 = 0.f, a3 = 0.f;
#pragma unroll
    for (int r = 0; r < NREP; r += 4) {
        a0 += __ldcg(p + (r + 0) * OUT_);
        a1 += __ldcg(p + (r + 1) * OUT_);
        a2 += __ldcg(p + (r + 2) * OUT_);
        a3 += __ldcg(p + (r + 3) * OUT_);
    }
#pragma unroll
    for (int r = 0; r < NREP; r++) p[r * OUT_] = 0.0f;
    float s = (a0 + a1) + (a2 + a3);
    float sq = s * s;
    float scale = sq / ((1.f + sq) * sqrtf(sq + 1e-7f));
    dst[idx] = scale * s;
}

__global__ __launch_bounds__(THREADS, 2) void k_fused(const float* __restrict__ X,
                                                      const float* __restrict__ W,
                                                      float* __restrict__ dout) {
    extern __shared__ float smem[];
    float* s_x = smem;                 // staged ONCE, read by all 3 passes
    float* s_w = smem + SX_SZ;
    float* s_e = s_w + SW_SZ;

    const int tid = threadIdx.x;
    const int n   = tid >> 5;
    const int l   = tid & 31;
    const int bb  = l & 15;
    const int dh  = l >> 4;
    const int cb  = blockIdx.x;        // 0..147
    const int bh  = blockIdx.y;        // 0..1
    const int fb  = bh * 148 + cb;     // flat block id 0..295
    int i0, ni;
    if (cb < 100) { i0 = cb * 28; ni = 28; }
    else          { i0 = 2800 + (cb - 100) * 27; ni = 27; }
    const int b1 = bh * 32 + bb;
    const int b2 = b1 + 16;

    // ---- stage x once
    {
        int nr = ni * 8;
        for (int idx = tid; idx < 32 * nr; idx += THREADS) {
            int lb = idx / nr;
            int r  = idx - lb * nr;
            s_x[lb * SX_STRIDE + r] = X[(size_t)(bh * 32 + lb) * (I_ * P_) + i0 * P_ + r];
        }
    }
    // (run_pass's internal __syncthreads covers this staging)

    run_pass<0>(W, s_x, s_w, s_e, i0, ni, tid, n, l, bb, dh, cb, b1, b2);
    grid_bar(1 * NBLK);
    if (fb < 32) do_squash(0, g_v, fb, tid);
    grid_bar(2 * NBLK);
    run_pass<1>(W, s_x, s_w, s_e, i0, ni, tid, n, l, bb, dh, cb, b1, b2);
    grid_bar(3 * NBLK);
    if (fb < 32) do_squash(1, g_v, fb, tid);
    grid_bar(4 * NBLK);
    run_pass<2>(W, s_x, s_w, s_e, i0, ni, tid, n, l, bb, dh, cb, b1, b2);
    grid_bar(5 * NBLK);
    if (fb < 32) do_squash(2, dout, fb, tid);

    // ---- end protocol: last finished block resets the barrier counter.
    // Every block has passed the final spin before incrementing g_done, so
    // no spinner can observe the reset.
    __syncthreads();
    if (tid == 0) {
        __threadfence();
        unsigned d = atomicAdd(&g_done, 1u) + 1u;
        if (d == NBLK) {
            g_gc = 0u;
            g_done = 0u;
            __threadfence();
        }
    }
}

extern "C" void kernel_launch(void* const* d_in, const int* in_sizes, int n_in,
                              void* d_out, int out_size) {
    const float* X = (const float*)d_in[0];
    const float* W = (const float*)d_in[1];
    if (n_in >= 2 && in_sizes[0] != B_ * I_ * P_) {
        const float* tmp = X; X = W; W = tmp;
    }

    dim3 gp(148, 2);
    k_fused<<<gp, THREADS, SMEM_BYTES>>>(X, W, (float*)d_out);
}